// round 1
// baseline (speedup 1.0000x reference)
#include <cuda_runtime.h>
#include <math.h>

// Problem constants
#define B_ 8
#define C_ 512
#define N_ 2048
#define CH_ (C_/2)   // 256

// Scratch in device globals (no runtime allocation allowed)
__device__ float g_Q[B_ * CH_ * N_];            // (B, 256, 2048)
__device__ float g_K[B_ * CH_ * N_];            // (B, 256, 2048)
__device__ float g_V[B_ * C_  * N_];            // (B, 512, 2048)
__device__ float g_A[(size_t)B_ * N_ * N_];     // (B, 2048, 2048)

// ---------------------------------------------------------------------------
// Generic tiled SGEMM: D[m,n] = alpha * sum_k Aop[m,k]*Bop[k,n] (+bias[m]) (+res[m,n])
//   TRA=false: Aop[m,k] = A[m*Kd + k]      TRA=true: Aop[m,k] = A[k*M + m]
//   TRB=false: Bop[k,n] = B[k*N + n]       TRB=true: Bop[k,n] = B[n*Kd + k]
// Tile: 64x64x16, 256 threads, 4x4 per-thread register block.
// Requires M,N % 64 == 0 and Kd % 16 == 0 (true for all uses here).
// ---------------------------------------------------------------------------
template<bool TRA, bool TRB, bool BIAS, bool RES>
__global__ void __launch_bounds__(256)
gemm_kernel(const float* __restrict__ Ag, const float* __restrict__ Bg,
            const float* __restrict__ bias, const float* __restrict__ res,
            float* __restrict__ Dg,
            int M, int N, int Kd, float alpha,
            size_t sA, size_t sB, size_t sRes, size_t sD)
{
    __shared__ float As[16][64];
    __shared__ float Bs[16][64];

    const int bz = blockIdx.z;
    const float* Ab = Ag + sA * bz;
    const float* Bb = Bg + sB * bz;
    float* Db = Dg + sD * bz;

    const int m0 = blockIdx.y * 64;
    const int n0 = blockIdx.x * 64;
    const int tid = threadIdx.x;
    const int tx = tid & 15;   // n direction
    const int ty = tid >> 4;   // m direction

    float acc[4][4] = {};

    for (int k0 = 0; k0 < Kd; k0 += 16) {
        // ---- Load A tile into As[k][m] ----
        if (!TRA) {
            int row = tid >> 2;            // 0..63 (m within tile)
            int j4  = (tid & 3) * 4;       // k within tile
            float4 v = *(const float4*)(Ab + (size_t)(m0 + row) * Kd + k0 + j4);
            As[j4 + 0][row] = v.x; As[j4 + 1][row] = v.y;
            As[j4 + 2][row] = v.z; As[j4 + 3][row] = v.w;
        } else {
            int k  = tid >> 4;             // 0..15
            int m4 = (tid & 15) * 4;       // m within tile
            float4 v = *(const float4*)(Ab + (size_t)(k0 + k) * M + m0 + m4);
            *(float4*)&As[k][m4] = v;
        }
        // ---- Load B tile into Bs[k][n] ----
        if (!TRB) {
            int k  = tid >> 4;
            int n4 = (tid & 15) * 4;
            float4 v = *(const float4*)(Bb + (size_t)(k0 + k) * N + n0 + n4);
            *(float4*)&Bs[k][n4] = v;
        } else {
            int nn = tid >> 2;             // 0..63 (n within tile)
            int j4 = (tid & 3) * 4;        // k within tile
            float4 v = *(const float4*)(Bb + (size_t)(n0 + nn) * Kd + k0 + j4);
            Bs[j4 + 0][nn] = v.x; Bs[j4 + 1][nn] = v.y;
            Bs[j4 + 2][nn] = v.z; Bs[j4 + 3][nn] = v.w;
        }
        __syncthreads();

        #pragma unroll
        for (int kk = 0; kk < 16; kk++) {
            float4 av4 = *(const float4*)&As[kk][ty * 4];
            float4 bv4 = *(const float4*)&Bs[kk][tx * 4];
            float av[4] = {av4.x, av4.y, av4.z, av4.w};
            float bw[4] = {bv4.x, bv4.y, bv4.z, bv4.w};
            #pragma unroll
            for (int i = 0; i < 4; i++)
                #pragma unroll
                for (int j = 0; j < 4; j++)
                    acc[i][j] += av[i] * bw[j];
        }
        __syncthreads();
    }

    // ---- Epilogue (vectorized float4 stores) ----
    #pragma unroll
    for (int i = 0; i < 4; i++) {
        int m = m0 + ty * 4 + i;
        float bb = BIAS ? bias[m] : 0.0f;
        size_t base = (size_t)m * N + n0 + tx * 4;
        float4 o;
        o.x = acc[i][0] * alpha + bb;
        o.y = acc[i][1] * alpha + bb;
        o.z = acc[i][2] * alpha + bb;
        o.w = acc[i][3] * alpha + bb;
        if (RES) {
            float4 r = *(const float4*)(res + sRes * bz + base);
            o.x += r.x; o.y += r.y; o.z += r.z; o.w += r.w;
        }
        *(float4*)(Db + base) = o;
    }
}

// ---------------------------------------------------------------------------
// Row softmax over last dim (M = 2048), one block (256 threads) per row.
// ---------------------------------------------------------------------------
__global__ void __launch_bounds__(256)
softmax_kernel(float* __restrict__ A)
{
    const int M = N_;
    float* row = A + (size_t)blockIdx.x * M;
    const int tid = threadIdx.x;

    float v[8];
    float mx = -1e30f;
    #pragma unroll
    for (int i = 0; i < 8; i++) {
        v[i] = row[tid + i * 256];
        mx = fmaxf(mx, v[i]);
    }
    // warp max
    #pragma unroll
    for (int o = 16; o; o >>= 1) mx = fmaxf(mx, __shfl_xor_sync(0xFFFFFFFFu, mx, o));
    __shared__ float smax[8];
    __shared__ float ssum[8];
    if ((tid & 31) == 0) smax[tid >> 5] = mx;
    __syncthreads();
    mx = smax[0];
    #pragma unroll
    for (int w = 1; w < 8; w++) mx = fmaxf(mx, smax[w]);

    float sum = 0.0f;
    #pragma unroll
    for (int i = 0; i < 8; i++) {
        v[i] = __expf(v[i] - mx);
        sum += v[i];
    }
    #pragma unroll
    for (int o = 16; o; o >>= 1) sum += __shfl_xor_sync(0xFFFFFFFFu, sum, o);
    if ((tid & 31) == 0) ssum[tid >> 5] = sum;
    __syncthreads();
    sum = ssum[0];
    #pragma unroll
    for (int w = 1; w < 8; w++) sum += ssum[w];

    float inv = 1.0f / sum;
    #pragma unroll
    for (int i = 0; i < 8; i++) row[tid + i * 256] = v[i] * inv;
}

// ---------------------------------------------------------------------------
// kernel_launch
// Inputs (metadata order): x, Wq, bq, Wk, bk, Wv, bv  (all fp32)
// Output: x + attention_out, shape (B, C, N) fp32
// ---------------------------------------------------------------------------
extern "C" void kernel_launch(void* const* d_in, const int* in_sizes, int n_in,
                              void* d_out, int out_size)
{
    const float* x  = (const float*)d_in[0];
    const float* Wq = (const float*)d_in[1];
    const float* bq = (const float*)d_in[2];
    const float* Wk = (const float*)d_in[3];
    const float* bk = (const float*)d_in[4];
    const float* Wv = (const float*)d_in[5];
    const float* bv = (const float*)d_in[6];
    float* out = (float*)d_out;

    float *Qp, *Kp, *Vp, *Ap;
    cudaGetSymbolAddress((void**)&Qp, g_Q);
    cudaGetSymbolAddress((void**)&Kp, g_K);
    cudaGetSymbolAddress((void**)&Vp, g_V);
    cudaGetSymbolAddress((void**)&Ap, g_A);

    const size_t sX = (size_t)C_ * N_;   // x / V / out per-batch stride
    const size_t sH = (size_t)CH_ * N_;  // Q/K per-batch stride
    const size_t sAm = (size_t)N_ * N_;  // scores per-batch stride
    dim3 blk(256);

    // Q = Wq @ x + bq   (256 x 2048, K=512)
    gemm_kernel<false, false, true, false><<<dim3(N_/64, CH_/64, B_), blk>>>(
        Wq, x, bq, nullptr, Qp, CH_, N_, C_, 1.0f, 0, sX, 0, sH);
    // K = Wk @ x + bk
    gemm_kernel<false, false, true, false><<<dim3(N_/64, CH_/64, B_), blk>>>(
        Wk, x, bk, nullptr, Kp, CH_, N_, C_, 1.0f, 0, sX, 0, sH);
    // V = Wv @ x + bv   (512 x 2048, K=512)
    gemm_kernel<false, false, true, false><<<dim3(N_/64, C_/64, B_), blk>>>(
        Wv, x, bv, nullptr, Vp, C_, N_, C_, 1.0f, 0, sX, 0, sX);

    // Scores: A[n,m] = (1/16) * sum_c Q[c,n] * K[c,m]   (2048 x 2048, K=256)
    gemm_kernel<true, false, false, false><<<dim3(N_/64, N_/64, B_), blk>>>(
        Qp, Kp, nullptr, nullptr, Ap, N_, N_, CH_, 0.0625f, sH, sH, 0, sAm);

    // Row softmax over m
    softmax_kernel<<<B_ * N_, blk>>>(Ap);

    // out[c,n] = x[c,n] + sum_m V[c,m] * A[n,m]   (512 x 2048, K=2048, B trans)
    gemm_kernel<false, true, false, true><<<dim3(N_/64, C_/64, B_), blk>>>(
        Vp, Ap, nullptr, x, out, C_, N_, N_, 1.0f, sX, sAm, sX, sX);
}

// round 2
// speedup vs baseline: 3.6679x; 3.6679x over previous
#include <cuda_runtime.h>
#include <cuda_bf16.h>
#include <mma.h>
#include <math.h>

using namespace nvcuda;
typedef __nv_bfloat16 bf16;

#define B_ 8
#define C_ 512
#define N_ 2048
#define CH_ 256   // C/2

// ---- device-global scratch (no runtime allocation allowed) ----
__device__ bf16  g_xb[B_ * C_ * N_];            // x in bf16
__device__ bf16  g_Wqb[CH_ * C_];
__device__ bf16  g_Wkb[CH_ * C_];
__device__ bf16  g_Wvb[C_ * C_];
__device__ bf16  g_Q[B_ * CH_ * N_];            // (B, 256, 2048) bf16
__device__ bf16  g_K[B_ * CH_ * N_];
__device__ bf16  g_V[B_ * C_ * N_];             // (B, 512, 2048) bf16
__device__ float g_S[(size_t)B_ * N_ * N_];     // scores fp32
__device__ bf16  g_P[(size_t)B_ * N_ * N_];     // softmax probs bf16

// ---------------------------------------------------------------------------
// fp32 -> bf16 conversion (vectorized)
// ---------------------------------------------------------------------------
__global__ void cvt_kernel(const float4* __restrict__ src,
                           __nv_bfloat162* __restrict__ dst, int n4)
{
    int i = blockIdx.x * blockDim.x + threadIdx.x;
    if (i < n4) {
        float4 v = src[i];
        dst[2 * i]     = __float22bfloat162_rn(make_float2(v.x, v.y));
        dst[2 * i + 1] = __float22bfloat162_rn(make_float2(v.z, v.w));
    }
}

// ---------------------------------------------------------------------------
// Projection: Y(O x N) = W(O x C) @ Xb(C x N) + bias,  bf16 in, bf16 out
// grid (N/64, O/64, B), 128 threads (4 warps, 2x2 warp grid, 32x32 per warp)
// ---------------------------------------------------------------------------
__global__ void __launch_bounds__(128)
proj_kernel(const bf16* __restrict__ W, const bf16* __restrict__ Xb,
            const float* __restrict__ bias, bf16* __restrict__ Y, int O)
{
    __shared__ bf16  As[64][40];   // W tile  [m][k]
    __shared__ bf16  Bs[32][72];   // X tile  [k][n]
    __shared__ float Cs[64][68];

    const bf16* Xbat = Xb + (size_t)blockIdx.z * C_ * N_;
    bf16* Ybat = Y + (size_t)blockIdx.z * O * N_;
    const int m0 = blockIdx.y * 64, n0 = blockIdx.x * 64;
    const int tid = threadIdx.x, warp = tid >> 5;
    const int wm = (warp >> 1) * 32, wn = (warp & 1) * 32;

    wmma::fragment<wmma::accumulator, 16, 16, 16, float> acc[2][2];
    #pragma unroll
    for (int i = 0; i < 2; i++)
        #pragma unroll
        for (int j = 0; j < 2; j++) wmma::fill_fragment(acc[i][j], 0.0f);

    for (int k0 = 0; k0 < C_; k0 += 32) {
        #pragma unroll
        for (int it = 0; it < 2; it++) {           // W tile: 64x32
            int q = tid + it * 128;
            int row = q >> 2, c8 = (q & 3) * 8;
            *(uint4*)&As[row][c8] = *(const uint4*)&W[(size_t)(m0 + row) * C_ + k0 + c8];
        }
        #pragma unroll
        for (int it = 0; it < 2; it++) {           // X tile: 32x64
            int q = tid + it * 128;
            int row = q >> 3, n8 = (q & 7) * 8;
            *(uint4*)&Bs[row][n8] = *(const uint4*)&Xbat[(size_t)(k0 + row) * N_ + n0 + n8];
        }
        __syncthreads();
        #pragma unroll
        for (int ks = 0; ks < 32; ks += 16) {
            wmma::fragment<wmma::matrix_a, 16, 16, 16, bf16, wmma::row_major> a[2];
            wmma::fragment<wmma::matrix_b, 16, 16, 16, bf16, wmma::row_major> b[2];
            wmma::load_matrix_sync(a[0], &As[wm][ks], 40);
            wmma::load_matrix_sync(a[1], &As[wm + 16][ks], 40);
            wmma::load_matrix_sync(b[0], &Bs[ks][wn], 72);
            wmma::load_matrix_sync(b[1], &Bs[ks][wn + 16], 72);
            #pragma unroll
            for (int i = 0; i < 2; i++)
                #pragma unroll
                for (int j = 0; j < 2; j++)
                    wmma::mma_sync(acc[i][j], a[i], b[j], acc[i][j]);
        }
        __syncthreads();
    }

    #pragma unroll
    for (int i = 0; i < 2; i++)
        #pragma unroll
        for (int j = 0; j < 2; j++)
            wmma::store_matrix_sync(&Cs[wm + i * 16][wn + j * 16], acc[i][j], 68,
                                    wmma::mem_row_major);
    __syncthreads();
    #pragma unroll
    for (int it = 0; it < 32; it++) {
        int idx = tid + it * 128;
        int row = idx >> 6, col = idx & 63;
        float v = Cs[row][col] + bias[m0 + row];
        Ybat[(size_t)(m0 + row) * N_ + n0 + col] = __float2bfloat16(v);
    }
}

// ---------------------------------------------------------------------------
// Scores: S[n,m] = (1/16) * sum_c Q[c,n] * K[c,m]   (fp32 out)
// grid (N/64 over m, N/64 over n, B)
// ---------------------------------------------------------------------------
__global__ void __launch_bounds__(128)
scores_kernel(const bf16* __restrict__ Q, const bf16* __restrict__ K,
              float* __restrict__ S)
{
    __shared__ bf16 Asc[32][72];   // Q tile [c][n]  (col-major for A op)
    __shared__ bf16 Bs[32][72];    // K tile [c][m]

    const bf16* Qb = Q + (size_t)blockIdx.z * CH_ * N_;
    const bf16* Kb = K + (size_t)blockIdx.z * CH_ * N_;
    float* Sb = S + (size_t)blockIdx.z * N_ * N_;
    const int n0 = blockIdx.y * 64, m0 = blockIdx.x * 64;
    const int tid = threadIdx.x, warp = tid >> 5;
    const int wm = (warp >> 1) * 32, wn = (warp & 1) * 32;

    wmma::fragment<wmma::accumulator, 16, 16, 16, float> acc[2][2];
    #pragma unroll
    for (int i = 0; i < 2; i++)
        #pragma unroll
        for (int j = 0; j < 2; j++) wmma::fill_fragment(acc[i][j], 0.0f);

    for (int k0 = 0; k0 < CH_; k0 += 32) {
        #pragma unroll
        for (int it = 0; it < 2; it++) {
            int q = tid + it * 128;
            int row = q >> 3, c8 = (q & 7) * 8;
            *(uint4*)&Asc[row][c8] = *(const uint4*)&Qb[(size_t)(k0 + row) * N_ + n0 + c8];
            *(uint4*)&Bs[row][c8]  = *(const uint4*)&Kb[(size_t)(k0 + row) * N_ + m0 + c8];
        }
        __syncthreads();
        #pragma unroll
        for (int ks = 0; ks < 32; ks += 16) {
            wmma::fragment<wmma::matrix_a, 16, 16, 16, bf16, wmma::col_major> a[2];
            wmma::fragment<wmma::matrix_b, 16, 16, 16, bf16, wmma::row_major> b[2];
            wmma::load_matrix_sync(a[0], &Asc[ks][wm], 72);
            wmma::load_matrix_sync(a[1], &Asc[ks][wm + 16], 72);
            wmma::load_matrix_sync(b[0], &Bs[ks][wn], 72);
            wmma::load_matrix_sync(b[1], &Bs[ks][wn + 16], 72);
            #pragma unroll
            for (int i = 0; i < 2; i++)
                #pragma unroll
                for (int j = 0; j < 2; j++)
                    wmma::mma_sync(acc[i][j], a[i], b[j], acc[i][j]);
        }
        __syncthreads();
    }

    #pragma unroll
    for (int i = 0; i < 2; i++)
        #pragma unroll
        for (int j = 0; j < 2; j++) {
            #pragma unroll
            for (int t = 0; t < acc[i][j].num_elements; t++) acc[i][j].x[t] *= 0.0625f;
            wmma::store_matrix_sync(&Sb[(size_t)(n0 + wm + i * 16) * N_ + m0 + wn + j * 16],
                                    acc[i][j], N_, wmma::mem_row_major);
        }
}

// ---------------------------------------------------------------------------
// Softmax over last dim (2048), fp32 in, bf16 out. One 256-thread block/row.
// ---------------------------------------------------------------------------
__global__ void __launch_bounds__(256)
softmax_kernel(const float* __restrict__ S, bf16* __restrict__ P)
{
    const float* row = S + (size_t)blockIdx.x * N_;
    bf16* prow = P + (size_t)blockIdx.x * N_;
    const int tid = threadIdx.x;

    float v[8];
    float mx = -1e30f;
    #pragma unroll
    for (int i = 0; i < 8; i++) { v[i] = row[tid + i * 256]; mx = fmaxf(mx, v[i]); }
    #pragma unroll
    for (int o = 16; o; o >>= 1) mx = fmaxf(mx, __shfl_xor_sync(0xFFFFFFFFu, mx, o));
    __shared__ float smax[8], ssum[8];
    if ((tid & 31) == 0) smax[tid >> 5] = mx;
    __syncthreads();
    mx = smax[0];
    #pragma unroll
    for (int w = 1; w < 8; w++) mx = fmaxf(mx, smax[w]);

    float sum = 0.0f;
    #pragma unroll
    for (int i = 0; i < 8; i++) { v[i] = __expf(v[i] - mx); sum += v[i]; }
    #pragma unroll
    for (int o = 16; o; o >>= 1) sum += __shfl_xor_sync(0xFFFFFFFFu, sum, o);
    if ((tid & 31) == 0) ssum[tid >> 5] = sum;
    __syncthreads();
    sum = ssum[0];
    #pragma unroll
    for (int w = 1; w < 8; w++) sum += ssum[w];

    float inv = 1.0f / sum;
    #pragma unroll
    for (int i = 0; i < 8; i++)
        prow[tid + i * 256] = __float2bfloat16(v[i] * inv);
}

// ---------------------------------------------------------------------------
// out[c,n] = x[c,n] + sum_m V[c,m] * P[n,m]     (fp32 out)
// grid (N/64 over n, C/64 over c, B)
// ---------------------------------------------------------------------------
__global__ void __launch_bounds__(128)
av_kernel(const bf16* __restrict__ V, const bf16* __restrict__ P,
          const float* __restrict__ x, float* __restrict__ out)
{
    __shared__ bf16  As[64][40];   // V tile [c][m]
    __shared__ bf16  Bs[64][40];   // P tile [n][m]  (col-major for B op)
    __shared__ float Cs[64][68];

    const bf16* Vb = V + (size_t)blockIdx.z * C_ * N_;
    const bf16* Pb = P + (size_t)blockIdx.z * N_ * N_;
    const float* xb = x + (size_t)blockIdx.z * C_ * N_;
    float* ob = out + (size_t)blockIdx.z * C_ * N_;
    const int c0 = blockIdx.y * 64, n0 = blockIdx.x * 64;
    const int tid = threadIdx.x, warp = tid >> 5;
    const int wm = (warp >> 1) * 32, wn = (warp & 1) * 32;

    wmma::fragment<wmma::accumulator, 16, 16, 16, float> acc[2][2];
    #pragma unroll
    for (int i = 0; i < 2; i++)
        #pragma unroll
        for (int j = 0; j < 2; j++) wmma::fill_fragment(acc[i][j], 0.0f);

    for (int m0 = 0; m0 < N_; m0 += 32) {
        #pragma unroll
        for (int it = 0; it < 2; it++) {
            int q = tid + it * 128;
            int row = q >> 2, m8 = (q & 3) * 8;
            *(uint4*)&As[row][m8] = *(const uint4*)&Vb[(size_t)(c0 + row) * N_ + m0 + m8];
            *(uint4*)&Bs[row][m8] = *(const uint4*)&Pb[(size_t)(n0 + row) * N_ + m0 + m8];
        }
        __syncthreads();
        #pragma unroll
        for (int ks = 0; ks < 32; ks += 16) {
            wmma::fragment<wmma::matrix_a, 16, 16, 16, bf16, wmma::row_major> a[2];
            wmma::fragment<wmma::matrix_b, 16, 16, 16, bf16, wmma::col_major> b[2];
            wmma::load_matrix_sync(a[0], &As[wm][ks], 40);
            wmma::load_matrix_sync(a[1], &As[wm + 16][ks], 40);
            wmma::load_matrix_sync(b[0], &Bs[wn][ks], 40);
            wmma::load_matrix_sync(b[1], &Bs[wn + 16][ks], 40);
            #pragma unroll
            for (int i = 0; i < 2; i++)
                #pragma unroll
                for (int j = 0; j < 2; j++)
                    wmma::mma_sync(acc[i][j], a[i], b[j], acc[i][j]);
        }
        __syncthreads();
    }

    #pragma unroll
    for (int i = 0; i < 2; i++)
        #pragma unroll
        for (int j = 0; j < 2; j++)
            wmma::store_matrix_sync(&Cs[wm + i * 16][wn + j * 16], acc[i][j], 68,
                                    wmma::mem_row_major);
    __syncthreads();
    #pragma unroll
    for (int it = 0; it < 32; it++) {
        int idx = tid + it * 128;
        int row = idx >> 6, col = idx & 63;
        size_t off = (size_t)(c0 + row) * N_ + n0 + col;
        ob[off] = xb[off] + Cs[row][col];
    }
}

// ---------------------------------------------------------------------------
extern "C" void kernel_launch(void* const* d_in, const int* in_sizes, int n_in,
                              void* d_out, int out_size)
{
    const float* x  = (const float*)d_in[0];
    const float* Wq = (const float*)d_in[1];
    const float* bq = (const float*)d_in[2];
    const float* Wk = (const float*)d_in[3];
    const float* bk = (const float*)d_in[4];
    const float* Wv = (const float*)d_in[5];
    const float* bv = (const float*)d_in[6];
    float* out = (float*)d_out;

    bf16 *xb, *Wqb, *Wkb, *Wvb, *Qp, *Kp, *Vp, *Pp;
    float* Sp;
    cudaGetSymbolAddress((void**)&xb,  g_xb);
    cudaGetSymbolAddress((void**)&Wqb, g_Wqb);
    cudaGetSymbolAddress((void**)&Wkb, g_Wkb);
    cudaGetSymbolAddress((void**)&Wvb, g_Wvb);
    cudaGetSymbolAddress((void**)&Qp,  g_Q);
    cudaGetSymbolAddress((void**)&Kp,  g_K);
    cudaGetSymbolAddress((void**)&Vp,  g_V);
    cudaGetSymbolAddress((void**)&Sp,  g_S);
    cudaGetSymbolAddress((void**)&Pp,  g_P);

    // fp32 -> bf16 conversions
    {
        int n4 = (B_ * C_ * N_) / 4;
        cvt_kernel<<<(n4 + 255) / 256, 256>>>((const float4*)x, (__nv_bfloat162*)xb, n4);
        n4 = (CH_ * C_) / 4;
        cvt_kernel<<<(n4 + 255) / 256, 256>>>((const float4*)Wq, (__nv_bfloat162*)Wqb, n4);
        cvt_kernel<<<(n4 + 255) / 256, 256>>>((const float4*)Wk, (__nv_bfloat162*)Wkb, n4);
        n4 = (C_ * C_) / 4;
        cvt_kernel<<<(n4 + 255) / 256, 256>>>((const float4*)Wv, (__nv_bfloat162*)Wvb, n4);
    }

    dim3 blk(128);
    // Q, K, V projections
    proj_kernel<<<dim3(N_ / 64, CH_ / 64, B_), blk>>>(Wqb, xb, bq, Qp, CH_);
    proj_kernel<<<dim3(N_ / 64, CH_ / 64, B_), blk>>>(Wkb, xb, bk, Kp, CH_);
    proj_kernel<<<dim3(N_ / 64, C_  / 64, B_), blk>>>(Wvb, xb, bv, Vp, C_);

    // Scores
    scores_kernel<<<dim3(N_ / 64, N_ / 64, B_), blk>>>(Qp, Kp, Sp);

    // Softmax fp32 -> bf16 probs
    softmax_kernel<<<B_ * N_, 256>>>(Sp, Pp);

    // out = x + V @ P^T
    av_kernel<<<dim3(N_ / 64, C_ / 64, B_), blk>>>(Vp, Pp, x, out);
}

// round 4
// speedup vs baseline: 3.7526x; 1.0231x over previous
#include <cuda_runtime.h>
#include <cuda_bf16.h>
#include <mma.h>
#include <math.h>
#include <cstdint>
#include <type_traits>

using namespace nvcuda;
typedef __nv_bfloat16 bf16;

#define B_ 8
#define C_ 512
#define N_ 2048
#define CH_ 256   // C/2

// ---- device-global scratch (no runtime allocation allowed) ----
__device__ bf16  g_xb[B_ * C_ * N_];
__device__ bf16  g_Wqb[CH_ * C_];
__device__ bf16  g_Wkb[CH_ * C_];
__device__ bf16  g_Wvb[C_ * C_];
__device__ bf16  g_Q[B_ * CH_ * N_];
__device__ bf16  g_K[B_ * CH_ * N_];
__device__ bf16  g_V[B_ * C_ * N_];
__device__ float g_S[(size_t)B_ * N_ * N_];
__device__ bf16  g_P[(size_t)B_ * N_ * N_];

// ---------------------------------------------------------------------------
// cp.async helpers
// ---------------------------------------------------------------------------
__device__ __forceinline__ void cp_async16(void* smem, const void* gmem) {
    unsigned s = (unsigned)__cvta_generic_to_shared(smem);
    asm volatile("cp.async.cg.shared.global [%0], [%1], 16;\n" :: "r"(s), "l"(gmem));
}
__device__ __forceinline__ void cp_commit() {
    asm volatile("cp.async.commit_group;\n");
}
template<int NW> __device__ __forceinline__ void cp_wait() {
    asm volatile("cp.async.wait_group %0;\n" :: "n"(NW));
}

// ---------------------------------------------------------------------------
// fp32 -> bf16 conversion (vectorized)
// ---------------------------------------------------------------------------
__global__ void cvt_kernel(const float4* __restrict__ src,
                           __nv_bfloat162* __restrict__ dst, int n4)
{
    int i = blockIdx.x * blockDim.x + threadIdx.x;
    if (i < n4) {
        float4 v = src[i];
        dst[2 * i]     = __float22bfloat162_rn(make_float2(v.x, v.y));
        dst[2 * i + 1] = __float22bfloat162_rn(make_float2(v.z, v.w));
    }
}

// ---------------------------------------------------------------------------
// One 32-wide K-step of MMA work for this warp
// ---------------------------------------------------------------------------
template<bool TRA, bool TRB>
__device__ __forceinline__ void mma_step(
    const bf16* __restrict__ As, const bf16* __restrict__ Bs,
    int s, int ks, int wm, int wn,
    wmma::fragment<wmma::accumulator, 16, 16, 16, float> (&acc)[4][2])
{
    using ALay = typename std::conditional<TRA, wmma::col_major, wmma::row_major>::type;
    using BLay = typename std::conditional<TRB, wmma::col_major, wmma::row_major>::type;
    wmma::fragment<wmma::matrix_a, 16, 16, 16, bf16, ALay> a[4];
    wmma::fragment<wmma::matrix_b, 16, 16, 16, bf16, BLay> b[2];
    #pragma unroll
    for (int i = 0; i < 4; i++)
        wmma::load_matrix_sync(a[i],
            TRA ? &As[(s * 32 + ks) * 136 + wm + i * 16]
                : &As[(s * 128 + wm + i * 16) * 40 + ks],
            TRA ? 136 : 40);
    #pragma unroll
    for (int j = 0; j < 2; j++)
        wmma::load_matrix_sync(b[j],
            TRB ? &Bs[(s * 128 + wn + j * 16) * 40 + ks]
                : &Bs[(s * 32 + ks) * 136 + wn + j * 16],
            TRB ? 40 : 136);
    #pragma unroll
    for (int i = 0; i < 4; i++)
        #pragma unroll
        for (int j = 0; j < 2; j++)
            wmma::mma_sync(acc[i][j], a[i], b[j], acc[i][j]);
}

// ---------------------------------------------------------------------------
// 128x128x32 double-buffered bf16 GEMM.
//   TRA: A is [k][m] in gmem (col-major op A), else [m][k]
//   TRB: B is [n][k] in gmem (col-major op B), else [k][n]
//   MODE 0: fp32 out, scaled by alpha (direct store)
//   MODE 1: bf16 out, + bias[m]
//   MODE 2: fp32 out, + res[m][n]  (residual)
// Requires M%128==0, N%128==0, K%32==0.
// ---------------------------------------------------------------------------
template<bool TRA, bool TRB, int MODE>
__global__ void __launch_bounds__(256)
gemm128(const bf16* __restrict__ Ag, const bf16* __restrict__ Bg,
        const float* __restrict__ bias, const float* __restrict__ res,
        void* __restrict__ Dg, int M, int N, int K, int lda, int ldb,
        float alpha, size_t sA, size_t sB, size_t sD, size_t sRes)
{
    constexpr int AELEM = TRA ? 2 * 32 * 136 : 2 * 128 * 40;
    constexpr int BELEM = TRB ? 2 * 128 * 40 : 2 * 32 * 136;
    __shared__ alignas(16) bf16 As[AELEM];
    __shared__ alignas(16) bf16 Bs[BELEM];

    const int bz = blockIdx.z;
    const bf16* Ab = Ag + sA * bz;
    const bf16* Bb = Bg + sB * bz;
    const int m0 = blockIdx.y * 128, n0 = blockIdx.x * 128;
    const int tid = threadIdx.x, warp = tid >> 5, lane = tid & 31;
    const int wm = (warp >> 2) * 64, wn = (warp & 3) * 32;

    auto loadA = [&](int k0, int s) {
        #pragma unroll
        for (int it = 0; it < 2; it++) {
            int q = tid + it * 256;
            if (!TRA) {
                int row = q >> 2, kc = (q & 3) * 8;
                cp_async16(&As[(s * 128 + row) * 40 + kc],
                           Ab + (size_t)(m0 + row) * lda + k0 + kc);
            } else {
                int row = q >> 4, mc = (q & 15) * 8;
                cp_async16(&As[(s * 32 + row) * 136 + mc],
                           Ab + (size_t)(k0 + row) * lda + m0 + mc);
            }
        }
    };
    auto loadB = [&](int k0, int s) {
        #pragma unroll
        for (int it = 0; it < 2; it++) {
            int q = tid + it * 256;
            if (!TRB) {
                int row = q >> 4, nc = (q & 15) * 8;
                cp_async16(&Bs[(s * 32 + row) * 136 + nc],
                           Bb + (size_t)(k0 + row) * ldb + n0 + nc);
            } else {
                int row = q >> 2, kc = (q & 3) * 8;
                cp_async16(&Bs[(s * 128 + row) * 40 + kc],
                           Bb + (size_t)(n0 + row) * ldb + k0 + kc);
            }
        }
    };

    wmma::fragment<wmma::accumulator, 16, 16, 16, float> acc[4][2];
    #pragma unroll
    for (int i = 0; i < 4; i++)
        #pragma unroll
        for (int j = 0; j < 2; j++) wmma::fill_fragment(acc[i][j], 0.0f);

    const int ntiles = K / 32;
    loadA(0, 0); loadB(0, 0); cp_commit();

    for (int t = 0; t < ntiles; t++) {
        int s = t & 1;
        if (t + 1 < ntiles) {
            loadA((t + 1) * 32, s ^ 1); loadB((t + 1) * 32, s ^ 1); cp_commit();
            cp_wait<1>();
        } else {
            cp_wait<0>();
        }
        __syncthreads();
        mma_step<TRA, TRB>(As, Bs, s, 0,  wm, wn, acc);
        mma_step<TRA, TRB>(As, Bs, s, 16, wm, wn, acc);
        __syncthreads();
    }

    // ---- Epilogue ----
    if (MODE == 0) {
        float* D = (float*)Dg + sD * bz;
        #pragma unroll
        for (int i = 0; i < 4; i++)
            #pragma unroll
            for (int j = 0; j < 2; j++) {
                #pragma unroll
                for (int t = 0; t < acc[i][j].num_elements; t++) acc[i][j].x[t] *= alpha;
                wmma::store_matrix_sync(
                    &D[(size_t)(m0 + wm + i * 16) * N + n0 + wn + j * 16],
                    acc[i][j], N, wmma::mem_row_major);
            }
    } else {
        // per-warp 16x16 fp32 patch, reusing As (all async groups drained, synced)
        float* patch = reinterpret_cast<float*>(As) + warp * 256;
        const int pr = lane >> 1, pc = (lane & 1) * 8;
        #pragma unroll
        for (int i = 0; i < 4; i++)
            #pragma unroll
            for (int j = 0; j < 2; j++) {
                wmma::store_matrix_sync(patch, acc[i][j], 16, wmma::mem_row_major);
                __syncwarp();
                int gm = m0 + wm + i * 16 + pr;
                int gn = n0 + wn + j * 16 + pc;
                if (MODE == 1) {
                    bf16* D = (bf16*)Dg + sD * bz;
                    float bb = bias[gm];
                    #pragma unroll
                    for (int e = 0; e < 8; e++)
                        D[(size_t)gm * N + gn + e] =
                            __float2bfloat16(patch[pr * 16 + pc + e] + bb);
                } else {
                    float* D = (float*)Dg + sD * bz;
                    const float* R = res + sRes * bz;
                    #pragma unroll
                    for (int e = 0; e < 8; e++)
                        D[(size_t)gm * N + gn + e] =
                            R[(size_t)gm * N + gn + e] + patch[pr * 16 + pc + e];
                }
                __syncwarp();
            }
    }
}

// ---------------------------------------------------------------------------
// Softmax over last dim (2048), fp32 in, bf16 out. One 256-thread block/row.
// ---------------------------------------------------------------------------
__global__ void __launch_bounds__(256)
softmax_kernel(const float* __restrict__ S, bf16* __restrict__ P)
{
    const float* row = S + (size_t)blockIdx.x * N_;
    bf16* prow = P + (size_t)blockIdx.x * N_;
    const int tid = threadIdx.x;

    float v[8];
    float mx = -1e30f;
    #pragma unroll
    for (int i = 0; i < 8; i++) { v[i] = row[tid + i * 256]; mx = fmaxf(mx, v[i]); }
    #pragma unroll
    for (int o = 16; o; o >>= 1) mx = fmaxf(mx, __shfl_xor_sync(0xFFFFFFFFu, mx, o));
    __shared__ float smax[8], ssum[8];
    if ((tid & 31) == 0) smax[tid >> 5] = mx;
    __syncthreads();
    mx = smax[0];
    #pragma unroll
    for (int w = 1; w < 8; w++) mx = fmaxf(mx, smax[w]);

    float sum = 0.0f;
    #pragma unroll
    for (int i = 0; i < 8; i++) { v[i] = __expf(v[i] - mx); sum += v[i]; }
    #pragma unroll
    for (int o = 16; o; o >>= 1) sum += __shfl_xor_sync(0xFFFFFFFFu, sum, o);
    if ((tid & 31) == 0) ssum[tid >> 5] = sum;
    __syncthreads();
    sum = ssum[0];
    #pragma unroll
    for (int w = 1; w < 8; w++) sum += ssum[w];

    float inv = 1.0f / sum;
    #pragma unroll
    for (int i = 0; i < 8; i++)
        prow[tid + i * 256] = __float2bfloat16(v[i] * inv);
}

// ---------------------------------------------------------------------------
extern "C" void kernel_launch(void* const* d_in, const int* in_sizes, int n_in,
                              void* d_out, int out_size)
{
    const float* x  = (const float*)d_in[0];
    const float* Wq = (const float*)d_in[1];
    const float* bq = (const float*)d_in[2];
    const float* Wk = (const float*)d_in[3];
    const float* bk = (const float*)d_in[4];
    const float* Wv = (const float*)d_in[5];
    const float* bv = (const float*)d_in[6];
    float* out = (float*)d_out;

    bf16 *xb, *Wqb, *Wkb, *Wvb, *Qp, *Kp, *Vp, *Pp;
    float* Sp;
    cudaGetSymbolAddress((void**)&xb,  g_xb);
    cudaGetSymbolAddress((void**)&Wqb, g_Wqb);
    cudaGetSymbolAddress((void**)&Wkb, g_Wkb);
    cudaGetSymbolAddress((void**)&Wvb, g_Wvb);
    cudaGetSymbolAddress((void**)&Qp,  g_Q);
    cudaGetSymbolAddress((void**)&Kp,  g_K);
    cudaGetSymbolAddress((void**)&Vp,  g_V);
    cudaGetSymbolAddress((void**)&Sp,  g_S);
    cudaGetSymbolAddress((void**)&Pp,  g_P);

    // fp32 -> bf16 conversions
    {
        int n4 = (B_ * C_ * N_) / 4;
        cvt_kernel<<<(n4 + 255) / 256, 256>>>((const float4*)x, (__nv_bfloat162*)xb, n4);
        n4 = (CH_ * C_) / 4;
        cvt_kernel<<<(n4 + 255) / 256, 256>>>((const float4*)Wq, (__nv_bfloat162*)Wqb, n4);
        cvt_kernel<<<(n4 + 255) / 256, 256>>>((const float4*)Wk, (__nv_bfloat162*)Wkb, n4);
        n4 = (C_ * C_) / 4;
        cvt_kernel<<<(n4 + 255) / 256, 256>>>((const float4*)Wv, (__nv_bfloat162*)Wvb, n4);
    }

    const size_t sX = (size_t)C_ * N_;
    const size_t sH = (size_t)CH_ * N_;
    const size_t sS = (size_t)N_ * N_;

    // Projections: Y = W @ xb + b    (bf16 out)
    gemm128<false, false, 1><<<dim3(N_ / 128, CH_ / 128, B_), 256>>>(
        Wqb, xb, bq, nullptr, Qp, CH_, N_, C_, C_, N_, 1.0f, 0, sX, sH, 0);
    gemm128<false, false, 1><<<dim3(N_ / 128, CH_ / 128, B_), 256>>>(
        Wkb, xb, bk, nullptr, Kp, CH_, N_, C_, C_, N_, 1.0f, 0, sX, sH, 0);
    gemm128<false, false, 1><<<dim3(N_ / 128, C_ / 128, B_), 256>>>(
        Wvb, xb, bv, nullptr, Vp, C_, N_, C_, C_, N_, 1.0f, 0, sX, sX, 0);

    // Scores: S[n,m] = (1/16) * sum_c Q[c,n] K[c,m]   (fp32 out)
    gemm128<true, false, 0><<<dim3(N_ / 128, N_ / 128, B_), 256>>>(
        Qp, Kp, nullptr, nullptr, Sp, N_, N_, CH_, N_, N_, 0.0625f, sH, sH, sS, 0);

    // Softmax fp32 -> bf16 probs
    softmax_kernel<<<B_ * N_, 256>>>(Sp, Pp);

    // out[c,n] = x[c,n] + sum_m V[c,m] P[n,m]
    gemm128<false, true, 2><<<dim3(N_ / 128, C_ / 128, B_), 256>>>(
        Vp, Pp, nullptr, x, out, C_, N_, N_, N_, N_, 1.0f, sX, sS, sX, sX);
}

// round 6
// speedup vs baseline: 6.9837x; 1.8610x over previous
#include <cuda_runtime.h>
#include <cuda_bf16.h>
#include <cstdint>
#include <math.h>

typedef __nv_bfloat16 bf16;

#define B_ 8
#define C_ 512
#define N_ 2048
#define CH_ 256

// ---- device-global scratch ----
__device__ bf16  g_xt[B_ * N_ * C_];            // [n][c] bf16
__device__ bf16  g_Wq[CH_ * C_];
__device__ bf16  g_Wk[CH_ * C_];
__device__ bf16  g_Wv[C_ * C_];
__device__ bf16  g_Qt[B_ * N_ * CH_];           // [n][c]
__device__ bf16  g_Kt[B_ * N_ * CH_];           // [m][c]
__device__ bf16  g_V [B_ * C_ * N_];            // [c][m]
__device__ float g_S [(size_t)B_ * N_ * N_];    // [n][m]
__device__ bf16  g_P [(size_t)B_ * N_ * N_];    // [n][m]

// ===========================================================================
// PTX helpers
// ===========================================================================
__device__ __forceinline__ uint32_t smem_u32(const void* p) {
    uint32_t a;
    asm("{ .reg .u64 t; cvta.to.shared.u64 t, %1; cvt.u32.u64 %0, t; }"
        : "=r"(a) : "l"(p));
    return a;
}
__device__ __forceinline__ void cp_async16(uint32_t dst, const void* src) {
    asm volatile("cp.async.cg.shared.global [%0], [%1], 16;\n" :: "r"(dst), "l"(src));
}
__device__ __forceinline__ void cp_commit() {
    asm volatile("cp.async.commit_group;\n");
}
template<int NW> __device__ __forceinline__ void cp_wait() {
    asm volatile("cp.async.wait_group %0;\n" :: "n"(NW));
}
__device__ __forceinline__ void ldsm4(uint32_t* r, uint32_t addr) {
    asm volatile("ldmatrix.sync.aligned.m8n8.x4.shared.b16 {%0,%1,%2,%3}, [%4];\n"
                 : "=r"(r[0]), "=r"(r[1]), "=r"(r[2]), "=r"(r[3]) : "r"(addr));
}
__device__ __forceinline__ void mma16816(float* c, const uint32_t* a,
                                         uint32_t b0, uint32_t b1) {
    asm volatile(
        "mma.sync.aligned.m16n8k16.row.col.f32.bf16.bf16.f32 "
        "{%0,%1,%2,%3}, {%4,%5,%6,%7}, {%8,%9}, {%0,%1,%2,%3};\n"
        : "+f"(c[0]), "+f"(c[1]), "+f"(c[2]), "+f"(c[3])
        : "r"(a[0]), "r"(a[1]), "r"(a[2]), "r"(a[3]), "r"(b0), "r"(b1));
}

// ===========================================================================
// K-major SS GEMM via mma.sync:  D[i,j] = alpha * sum_k A[i,k]*B[j,k] + epi
// CTA 128x128, warp tile 64x32 (2x4 warp grid), K-chunks of 64, 3-stage
// cp.async pipeline, XOR-swizzled smem (128-byte rows).
//   MODE 0: fp32 out * alpha
//   MODE 1: bf16 out + bias[j]
//   MODE 2: bf16 out + bias[i]
//   MODE 3: fp32 out + res[i][j]
// Requires rows%128==0, cols%128==0, Ktot%64==0.
// ===========================================================================
#define NSTG 3
#define SMEMB (NSTG * 32768)

template<int MODE>
__global__ void __launch_bounds__(256)
mma_gemm(const bf16* __restrict__ Ag, const bf16* __restrict__ Bg,
         const float* __restrict__ bias, const float* __restrict__ res,
         void* __restrict__ Dg, int Ktot, int lda, int ldb, int ldd,
         float alpha, size_t sA, size_t sB, size_t sD, size_t sRes)
{
    extern __shared__ char smem[];
    const uint32_t s0 = smem_u32(smem);

    const int tid = threadIdx.x, warp = tid >> 5, lane = tid & 31;
    const int bz = blockIdx.z;
    const int i0 = blockIdx.y * 128, j0 = blockIdx.x * 128;
    const bf16* Ab = Ag + sA * bz;
    const bf16* Bb = Bg + sB * bz;

    const int wm = (warp >> 2) * 64;    // warp row offset (0/64)
    const int wn = (warp & 3) * 32;     // warp col offset (0/32/64/96)

    // ldmatrix lane-derived addressing
    const int rAl = lane & 15;            // A row within 16
    const int aHalf = lane >> 4;          // A k-chunk half
    const int rBl = (lane & 7) + ((lane & 16) >> 1);   // B row within 16
    const int bHalf = (lane >> 3) & 1;    // B k-chunk half

    float acc[4][4][4];
    #pragma unroll
    for (int mi = 0; mi < 4; mi++)
        #pragma unroll
        for (int ni = 0; ni < 4; ni++)
            #pragma unroll
            for (int e = 0; e < 4; e++) acc[mi][ni][e] = 0.0f;

    auto load_stage = [&](int t) {
        const uint32_t base = s0 + (uint32_t)(t % NSTG) * 32768u;
        const int k0 = t * 64;
        #pragma unroll
        for (int it = 0; it < 8; it++) {
            int q = it * 256 + tid;
            int qq = q & 1023;
            int row = qq >> 3, c = qq & 7;
            uint32_t dst = base + (q < 1024 ? 0u : 16384u)
                         + (uint32_t)(row * 128 + ((c ^ (row & 7)) << 4));
            const bf16* src = (q < 1024)
                ? Ab + (size_t)(i0 + row) * lda + k0 + c * 8
                : Bb + (size_t)(j0 + row) * ldb + k0 + c * 8;
            cp_async16(dst, src);
        }
        cp_commit();
    };

    const int T = Ktot >> 6;
    load_stage(0);
    if (T > 1) load_stage(1); else cp_commit();

    for (int t = 0; t < T; t++) {
        if (t + 2 < T) load_stage(t + 2); else cp_commit();
        cp_wait<2>();
        __syncthreads();

        const uint32_t sa = s0 + (uint32_t)(t % NSTG) * 32768u;
        const uint32_t sb = sa + 16384u;
        #pragma unroll
        for (int k16 = 0; k16 < 4; k16++) {
            uint32_t a[4][4], b[2][4];
            #pragma unroll
            for (int mi = 0; mi < 4; mi++) {
                int row = wm + mi * 16 + rAl;
                int ch = 2 * k16 + aHalf;
                ldsm4(a[mi], sa + (uint32_t)(row * 128 + ((ch ^ (row & 7)) << 4)));
            }
            #pragma unroll
            for (int nh = 0; nh < 2; nh++) {
                int row = wn + nh * 16 + rBl;
                int ch = 2 * k16 + bHalf;
                ldsm4(b[nh], sb + (uint32_t)(row * 128 + ((ch ^ (row & 7)) << 4)));
            }
            #pragma unroll
            for (int mi = 0; mi < 4; mi++)
                #pragma unroll
                for (int ni = 0; ni < 4; ni++)
                    mma16816(acc[mi][ni], a[mi],
                             b[ni >> 1][(ni & 1) * 2], b[ni >> 1][(ni & 1) * 2 + 1]);
        }
        __syncthreads();
    }

    // ---- Epilogue: direct register -> gmem ----
    const int er = lane >> 2;            // 0..7
    const int ec = 2 * (lane & 3);       // 0,2,4,6
    #pragma unroll
    for (int mi = 0; mi < 4; mi++)
        #pragma unroll
        for (int ni = 0; ni < 4; ni++) {
            const float* a4 = acc[mi][ni];
            int gm = i0 + wm + mi * 16 + er;
            int gn = j0 + wn + ni * 8 + ec;
            if (MODE == 0) {
                float* D = (float*)Dg + sD * bz;
                *(float2*)&D[(size_t)gm * ldd + gn] =
                    make_float2(a4[0] * alpha, a4[1] * alpha);
                *(float2*)&D[(size_t)(gm + 8) * ldd + gn] =
                    make_float2(a4[2] * alpha, a4[3] * alpha);
            } else if (MODE == 3) {
                float* D = (float*)Dg + sD * bz;
                const float* R = res + sRes * bz;
                float2 r0 = *(const float2*)&R[(size_t)gm * ldd + gn];
                float2 r1 = *(const float2*)&R[(size_t)(gm + 8) * ldd + gn];
                *(float2*)&D[(size_t)gm * ldd + gn] =
                    make_float2(r0.x + a4[0], r0.y + a4[1]);
                *(float2*)&D[(size_t)(gm + 8) * ldd + gn] =
                    make_float2(r1.x + a4[2], r1.y + a4[3]);
            } else {
                bf16* D = (bf16*)Dg + sD * bz;
                float b0, b1, b2, b3;
                if (MODE == 1) {
                    b0 = bias[gn]; b1 = bias[gn + 1]; b2 = b0; b3 = b1;
                } else {
                    b0 = b1 = bias[gm]; b2 = b3 = bias[gm + 8];
                }
                *(__nv_bfloat162*)&D[(size_t)gm * ldd + gn] =
                    __float22bfloat162_rn(make_float2(a4[0] + b0, a4[1] + b1));
                *(__nv_bfloat162*)&D[(size_t)(gm + 8) * ldd + gn] =
                    __float22bfloat162_rn(make_float2(a4[2] + b2, a4[3] + b3));
            }
        }
}

// ===========================================================================
// fp32 -> bf16 conversion (weights)
// ===========================================================================
__global__ void cvt_kernel(const float4* __restrict__ src,
                           __nv_bfloat162* __restrict__ dst, int n4)
{
    int i = blockIdx.x * blockDim.x + threadIdx.x;
    if (i < n4) {
        float4 v = src[i];
        dst[2 * i]     = __float22bfloat162_rn(make_float2(v.x, v.y));
        dst[2 * i + 1] = __float22bfloat162_rn(make_float2(v.z, v.w));
    }
}

// ===========================================================================
// x (B,C,N) fp32 -> xt (B,N,C) bf16 transpose
// ===========================================================================
__global__ void __launch_bounds__(256)
transpose_cvt(const float* __restrict__ x, bf16* __restrict__ xt)
{
    __shared__ float tile[32][33];
    const int b = blockIdx.z;
    const int c0 = blockIdx.y * 32, n0 = blockIdx.x * 32;
    const float* xb = x + (size_t)b * C_ * N_;
    bf16* xtb = xt + (size_t)b * N_ * C_;
    const int tx = threadIdx.x & 31, ty = threadIdx.x >> 5;
    #pragma unroll
    for (int i = 0; i < 4; i++)
        tile[ty + 8 * i][tx] = xb[(size_t)(c0 + ty + 8 * i) * N_ + n0 + tx];
    __syncthreads();
    #pragma unroll
    for (int i = 0; i < 4; i++)
        xtb[(size_t)(n0 + ty + 8 * i) * C_ + c0 + tx] =
            __float2bfloat16(tile[tx][ty + 8 * i]);
}

// ===========================================================================
// Softmax over last dim (2048), fp32 in, bf16 out.
// ===========================================================================
__global__ void __launch_bounds__(256)
softmax_kernel(const float* __restrict__ S, bf16* __restrict__ P)
{
    const float* row = S + (size_t)blockIdx.x * N_;
    bf16* prow = P + (size_t)blockIdx.x * N_;
    const int tid = threadIdx.x;

    float v[8];
    float mx = -1e30f;
    #pragma unroll
    for (int i = 0; i < 8; i++) { v[i] = row[tid + i * 256]; mx = fmaxf(mx, v[i]); }
    #pragma unroll
    for (int o = 16; o; o >>= 1) mx = fmaxf(mx, __shfl_xor_sync(0xFFFFFFFFu, mx, o));
    __shared__ float smax[8], ssum[8];
    if ((tid & 31) == 0) smax[tid >> 5] = mx;
    __syncthreads();
    mx = smax[0];
    #pragma unroll
    for (int w = 1; w < 8; w++) mx = fmaxf(mx, smax[w]);

    float sum = 0.0f;
    #pragma unroll
    for (int i = 0; i < 8; i++) { v[i] = __expf(v[i] - mx); sum += v[i]; }
    #pragma unroll
    for (int o = 16; o; o >>= 1) sum += __shfl_xor_sync(0xFFFFFFFFu, sum, o);
    if ((tid & 31) == 0) ssum[tid >> 5] = sum;
    __syncthreads();
    sum = ssum[0];
    #pragma unroll
    for (int w = 1; w < 8; w++) sum += ssum[w];

    float inv = 1.0f / sum;
    #pragma unroll
    for (int i = 0; i < 8; i++)
        prow[tid + i * 256] = __float2bfloat16(v[i] * inv);
}

// ===========================================================================
extern "C" void kernel_launch(void* const* d_in, const int* in_sizes, int n_in,
                              void* d_out, int out_size)
{
    const float* x  = (const float*)d_in[0];
    const float* Wq = (const float*)d_in[1];
    const float* bq = (const float*)d_in[2];
    const float* Wk = (const float*)d_in[3];
    const float* bk = (const float*)d_in[4];
    const float* Wv = (const float*)d_in[5];
    const float* bv = (const float*)d_in[6];
    float* out = (float*)d_out;

    bf16 *xt, *Wqb, *Wkb, *Wvb, *Qt, *Kt, *Vp, *Pp;
    float* Sp;
    cudaGetSymbolAddress((void**)&xt,  g_xt);
    cudaGetSymbolAddress((void**)&Wqb, g_Wq);
    cudaGetSymbolAddress((void**)&Wkb, g_Wk);
    cudaGetSymbolAddress((void**)&Wvb, g_Wv);
    cudaGetSymbolAddress((void**)&Qt,  g_Qt);
    cudaGetSymbolAddress((void**)&Kt,  g_Kt);
    cudaGetSymbolAddress((void**)&Vp,  g_V);
    cudaGetSymbolAddress((void**)&Sp,  g_S);
    cudaGetSymbolAddress((void**)&Pp,  g_P);

    cudaFuncSetAttribute(mma_gemm<0>, cudaFuncAttributeMaxDynamicSharedMemorySize, SMEMB);
    cudaFuncSetAttribute(mma_gemm<1>, cudaFuncAttributeMaxDynamicSharedMemorySize, SMEMB);
    cudaFuncSetAttribute(mma_gemm<2>, cudaFuncAttributeMaxDynamicSharedMemorySize, SMEMB);
    cudaFuncSetAttribute(mma_gemm<3>, cudaFuncAttributeMaxDynamicSharedMemorySize, SMEMB);

    // conversions
    {
        int n4 = (CH_ * C_) / 4;
        cvt_kernel<<<(n4 + 255) / 256, 256>>>((const float4*)Wq, (__nv_bfloat162*)Wqb, n4);
        cvt_kernel<<<(n4 + 255) / 256, 256>>>((const float4*)Wk, (__nv_bfloat162*)Wkb, n4);
        n4 = (C_ * C_) / 4;
        cvt_kernel<<<(n4 + 255) / 256, 256>>>((const float4*)Wv, (__nv_bfloat162*)Wvb, n4);
        transpose_cvt<<<dim3(N_ / 32, C_ / 32, B_), 256>>>(x, xt);
    }

    const size_t sXT = (size_t)N_ * C_;
    const size_t sQ  = (size_t)N_ * CH_;
    const size_t sX  = (size_t)C_ * N_;
    const size_t sS  = (size_t)N_ * N_;

    // Qt[n][o] = sum_c xt[n,c] Wq[o,c] + bq[o]    (bias over j)
    mma_gemm<1><<<dim3(CH_ / 128, N_ / 128, B_), 256, SMEMB>>>(
        xt, Wqb, bq, nullptr, Qt, C_, C_, C_, CH_, 1.0f, sXT, 0, sQ, 0);
    // Kt
    mma_gemm<1><<<dim3(CH_ / 128, N_ / 128, B_), 256, SMEMB>>>(
        xt, Wkb, bk, nullptr, Kt, C_, C_, C_, CH_, 1.0f, sXT, 0, sQ, 0);
    // V[o][n] = sum_c Wv[o,c] xt[n,c] + bv[o]     (bias over i)
    mma_gemm<2><<<dim3(N_ / 128, C_ / 128, B_), 256, SMEMB>>>(
        Wvb, xt, bv, nullptr, Vp, C_, C_, C_, N_, 1.0f, 0, sXT, sX, 0);
    // S[n][m] = (1/16) sum_c Qt[n,c] Kt[m,c]
    mma_gemm<0><<<dim3(N_ / 128, N_ / 128, B_), 256, SMEMB>>>(
        Qt, Kt, nullptr, nullptr, Sp, CH_, CH_, CH_, N_, 0.0625f, sQ, sQ, sS, 0);
    // softmax
    softmax_kernel<<<B_ * N_, 256>>>(Sp, Pp);
    // out[c][n] = x[c][n] + sum_m V[c,m] P[n,m]
    mma_gemm<3><<<dim3(N_ / 128, C_ / 128, B_), 256, SMEMB>>>(
        Vp, Pp, nullptr, x, out, N_, N_, N_, N_, 1.0f, sX, sS, sX, sX);
}

// round 8
// speedup vs baseline: 7.6314x; 1.0927x over previous
#include <cuda_runtime.h>
#include <cuda_bf16.h>
#include <cstdint>
#include <math.h>

typedef __nv_bfloat16 bf16;

#define B_ 8
#define C_ 512
#define N_ 2048
#define CH_ 256

// ---- device-global scratch ----
__device__ bf16  g_xt [B_ * N_ * C_];             // [n][c] bf16
__device__ bf16  g_Wqk[2 * CH_ * C_];             // rows 0-255 Wq, 256-511 Wk
__device__ bf16  g_Wv [C_ * C_];
__device__ float g_bqk[2 * CH_];                  // packed bq|bk
__device__ bf16  g_QK [B_ * N_ * C_];             // [n][0..255]=Q, [256..511]=K
__device__ bf16  g_V  [B_ * C_ * N_];             // [c][m]
__device__ float g_S  [(size_t)B_ * N_ * N_];     // [n][m]
__device__ bf16  g_P  [(size_t)B_ * N_ * N_];     // [n][m]

// ===========================================================================
// PTX helpers
// ===========================================================================
__device__ __forceinline__ uint32_t smem_u32(const void* p) {
    uint32_t a;
    asm("{ .reg .u64 t; cvta.to.shared.u64 t, %1; cvt.u32.u64 %0, t; }"
        : "=r"(a) : "l"(p));
    return a;
}
__device__ __forceinline__ void cp_async16(uint32_t dst, const void* src) {
    asm volatile("cp.async.cg.shared.global [%0], [%1], 16;\n" :: "r"(dst), "l"(src));
}
__device__ __forceinline__ void cp_commit() {
    asm volatile("cp.async.commit_group;\n");
}
template<int NW> __device__ __forceinline__ void cp_wait() {
    asm volatile("cp.async.wait_group %0;\n" :: "n"(NW));
}
__device__ __forceinline__ void ldsm4(uint32_t* r, uint32_t addr) {
    asm volatile("ldmatrix.sync.aligned.m8n8.x4.shared.b16 {%0,%1,%2,%3}, [%4];\n"
                 : "=r"(r[0]), "=r"(r[1]), "=r"(r[2]), "=r"(r[3]) : "r"(addr));
}
__device__ __forceinline__ void mma16816(float* c, const uint32_t* a,
                                         uint32_t b0, uint32_t b1) {
    asm volatile(
        "mma.sync.aligned.m16n8k16.row.col.f32.bf16.bf16.f32 "
        "{%0,%1,%2,%3}, {%4,%5,%6,%7}, {%8,%9}, {%0,%1,%2,%3};\n"
        : "+f"(c[0]), "+f"(c[1]), "+f"(c[2]), "+f"(c[3])
        : "r"(a[0]), "r"(a[1]), "r"(a[2]), "r"(a[3]), "r"(b0), "r"(b1));
}
__device__ __forceinline__ uint32_t pack_bf16x2(float lo, float hi) {
    __nv_bfloat162 h = __float22bfloat162_rn(make_float2(lo, hi));
    uint32_t u;
    memcpy(&u, &h, 4);
    return u;
}

// ===========================================================================
// K-major SS GEMM: D[i,j] = alpha * sum_k A[i,k]*B[j,k] + epilogue
// CTA 128x128, 4 warps (2x2), warp tile 64x64, K-chunks of 64, 3-stage
// cp.async pipeline, XOR-swizzled smem (128-byte rows).
//   MODE 0: fp32 out * alpha
//   MODE 1: bf16 out + bias[j]
//   MODE 2: bf16 out + bias[i]
//   MODE 3: fp32 out + res[i][j]
// ===========================================================================
#define NSTG 3
#define SMEMB (NSTG * 32768)

template<int MODE>
__global__ void __launch_bounds__(128, 2)
mma_gemm(const bf16* __restrict__ Ag, const bf16* __restrict__ Bg,
         const float* __restrict__ bias, const float* __restrict__ res,
         void* __restrict__ Dg, int Ktot, int lda, int ldb, int ldd,
         float alpha, size_t sA, size_t sB, size_t sD, size_t sRes)
{
    extern __shared__ char smem[];
    const uint32_t s0 = smem_u32(smem);

    const int tid = threadIdx.x, warp = tid >> 5, lane = tid & 31;
    const int bz = blockIdx.z;
    const int i0 = blockIdx.y * 128, j0 = blockIdx.x * 128;
    const bf16* Ab = Ag + sA * bz;
    const bf16* Bb = Bg + sB * bz;

    const int wm = (warp >> 1) * 64;    // warp row offset (0/64)
    const int wn = (warp & 1) * 64;     // warp col offset (0/64)

    const int rAl = lane & 15;
    const int aHalf = lane >> 4;
    const int rBl = (lane & 7) + ((lane & 16) >> 1);
    const int bHalf = (lane >> 3) & 1;

    float acc[4][8][4];
    #pragma unroll
    for (int mi = 0; mi < 4; mi++)
        #pragma unroll
        for (int ni = 0; ni < 8; ni++)
            #pragma unroll
            for (int e = 0; e < 4; e++) acc[mi][ni][e] = 0.0f;

    auto load_stage = [&](int t) {
        const uint32_t base = s0 + (uint32_t)(t % NSTG) * 32768u;
        const int k0 = t * 64;
        #pragma unroll
        for (int it = 0; it < 16; it++) {
            int q = it * 128 + tid;
            int qq = q & 1023;
            int row = qq >> 3, c = qq & 7;
            uint32_t dst = base + (q < 1024 ? 0u : 16384u)
                         + (uint32_t)(row * 128 + ((c ^ (row & 7)) << 4));
            const bf16* src = (q < 1024)
                ? Ab + (size_t)(i0 + row) * lda + k0 + c * 8
                : Bb + (size_t)(j0 + row) * ldb + k0 + c * 8;
            cp_async16(dst, src);
        }
        cp_commit();
    };

    const int T = Ktot >> 6;
    load_stage(0);
    if (T > 1) load_stage(1); else cp_commit();

    for (int t = 0; t < T; t++) {
        if (t + 2 < T) load_stage(t + 2); else cp_commit();
        cp_wait<2>();
        __syncthreads();

        const uint32_t sa = s0 + (uint32_t)(t % NSTG) * 32768u;
        const uint32_t sb = sa + 16384u;
        #pragma unroll
        for (int k16 = 0; k16 < 4; k16++) {
            uint32_t a[4][4], b[4][4];
            #pragma unroll
            for (int mi = 0; mi < 4; mi++) {
                int row = wm + mi * 16 + rAl;
                int ch = 2 * k16 + aHalf;
                ldsm4(a[mi], sa + (uint32_t)(row * 128 + ((ch ^ (row & 7)) << 4)));
            }
            #pragma unroll
            for (int nh = 0; nh < 4; nh++) {
                int row = wn + nh * 16 + rBl;
                int ch = 2 * k16 + bHalf;
                ldsm4(b[nh], sb + (uint32_t)(row * 128 + ((ch ^ (row & 7)) << 4)));
            }
            #pragma unroll
            for (int mi = 0; mi < 4; mi++)
                #pragma unroll
                for (int ni = 0; ni < 8; ni++)
                    mma16816(acc[mi][ni], a[mi],
                             b[ni >> 1][(ni & 1) * 2], b[ni >> 1][(ni & 1) * 2 + 1]);
        }
        __syncthreads();
    }

    // ---- Epilogue: direct register -> gmem ----
    const int er = lane >> 2;
    const int ec = 2 * (lane & 3);
    #pragma unroll
    for (int mi = 0; mi < 4; mi++)
        #pragma unroll
        for (int ni = 0; ni < 8; ni++) {
            const float* a4 = acc[mi][ni];
            int gm = i0 + wm + mi * 16 + er;
            int gn = j0 + wn + ni * 8 + ec;
            if (MODE == 0) {
                float* D = (float*)Dg + sD * bz;
                *(float2*)&D[(size_t)gm * ldd + gn] =
                    make_float2(a4[0] * alpha, a4[1] * alpha);
                *(float2*)&D[(size_t)(gm + 8) * ldd + gn] =
                    make_float2(a4[2] * alpha, a4[3] * alpha);
            } else if (MODE == 3) {
                float* D = (float*)Dg + sD * bz;
                const float* R = res + sRes * bz;
                float2 r0 = *(const float2*)&R[(size_t)gm * ldd + gn];
                float2 r1 = *(const float2*)&R[(size_t)(gm + 8) * ldd + gn];
                *(float2*)&D[(size_t)gm * ldd + gn] =
                    make_float2(r0.x + a4[0], r0.y + a4[1]);
                *(float2*)&D[(size_t)(gm + 8) * ldd + gn] =
                    make_float2(r1.x + a4[2], r1.y + a4[3]);
            } else {
                bf16* D = (bf16*)Dg + sD * bz;
                float b0, b1, b2, b3;
                if (MODE == 1) {
                    b0 = bias[gn]; b1 = bias[gn + 1]; b2 = b0; b3 = b1;
                } else {
                    b0 = b1 = bias[gm]; b2 = b3 = bias[gm + 8];
                }
                *(__nv_bfloat162*)&D[(size_t)gm * ldd + gn] =
                    __float22bfloat162_rn(make_float2(a4[0] + b0, a4[1] + b1));
                *(__nv_bfloat162*)&D[(size_t)(gm + 8) * ldd + gn] =
                    __float22bfloat162_rn(make_float2(a4[2] + b2, a4[3] + b3));
            }
        }
}

// ===========================================================================
// fp32 -> bf16 conversion (weights)
// ===========================================================================
__global__ void cvt_kernel(const float4* __restrict__ src,
                           __nv_bfloat162* __restrict__ dst, int n4)
{
    int i = blockIdx.x * blockDim.x + threadIdx.x;
    if (i < n4) {
        float4 v = src[i];
        dst[2 * i]     = __float22bfloat162_rn(make_float2(v.x, v.y));
        dst[2 * i + 1] = __float22bfloat162_rn(make_float2(v.z, v.w));
    }
}

// bias pack: g_bqk = [bq | bk]
__global__ void pack_bias(const float* __restrict__ bq, const float* __restrict__ bk,
                          float* __restrict__ dst)
{
    int i = threadIdx.x + blockIdx.x * blockDim.x;
    if (i < CH_) dst[i] = bq[i];
    else if (i < 2 * CH_) dst[i] = bk[i - CH_];
}

// ===========================================================================
// x (B,C,N) fp32 -> xt (B,N,C) bf16 transpose
// ===========================================================================
__global__ void __launch_bounds__(256)
transpose_cvt(const float* __restrict__ x, bf16* __restrict__ xt)
{
    __shared__ float tile[32][33];
    const int b = blockIdx.z;
    const int c0 = blockIdx.y * 32, n0 = blockIdx.x * 32;
    const float* xb = x + (size_t)b * C_ * N_;
    bf16* xtb = xt + (size_t)b * N_ * C_;
    const int tx = threadIdx.x & 31, ty = threadIdx.x >> 5;
    #pragma unroll
    for (int i = 0; i < 4; i++)
        tile[ty + 8 * i][tx] = xb[(size_t)(c0 + ty + 8 * i) * N_ + n0 + tx];
    __syncthreads();
    #pragma unroll
    for (int i = 0; i < 4; i++)
        xtb[(size_t)(n0 + ty + 8 * i) * C_ + c0 + tx] =
            __float2bfloat16(tile[tx][ty + 8 * i]);
}

// ===========================================================================
// Softmax over last dim (2048), fp32 in, bf16 out. Vectorized.
// ===========================================================================
__global__ void __launch_bounds__(256)
softmax_kernel(const float* __restrict__ S, bf16* __restrict__ P)
{
    const float4* row = (const float4*)(S + (size_t)blockIdx.x * N_);
    bf16* prow = P + (size_t)blockIdx.x * N_;
    const int tid = threadIdx.x;

    float4 v0 = row[tid];
    float4 v1 = row[tid + 256];
    float mx = fmaxf(fmaxf(fmaxf(v0.x, v0.y), fmaxf(v0.z, v0.w)),
                     fmaxf(fmaxf(v1.x, v1.y), fmaxf(v1.z, v1.w)));
    #pragma unroll
    for (int o = 16; o; o >>= 1) mx = fmaxf(mx, __shfl_xor_sync(0xFFFFFFFFu, mx, o));
    __shared__ float smax[8], ssum[8];
    if ((tid & 31) == 0) smax[tid >> 5] = mx;
    __syncthreads();
    mx = smax[0];
    #pragma unroll
    for (int w = 1; w < 8; w++) mx = fmaxf(mx, smax[w]);

    v0.x = __expf(v0.x - mx); v0.y = __expf(v0.y - mx);
    v0.z = __expf(v0.z - mx); v0.w = __expf(v0.w - mx);
    v1.x = __expf(v1.x - mx); v1.y = __expf(v1.y - mx);
    v1.z = __expf(v1.z - mx); v1.w = __expf(v1.w - mx);
    float sum = v0.x + v0.y + v0.z + v0.w + v1.x + v1.y + v1.z + v1.w;
    #pragma unroll
    for (int o = 16; o; o >>= 1) sum += __shfl_xor_sync(0xFFFFFFFFu, sum, o);
    if ((tid & 31) == 0) ssum[tid >> 5] = sum;
    __syncthreads();
    sum = ssum[0];
    #pragma unroll
    for (int w = 1; w < 8; w++) sum += ssum[w];

    float inv = 1.0f / sum;
    uint2 o0, o1;
    o0.x = pack_bf16x2(v0.x * inv, v0.y * inv);
    o0.y = pack_bf16x2(v0.z * inv, v0.w * inv);
    o1.x = pack_bf16x2(v1.x * inv, v1.y * inv);
    o1.y = pack_bf16x2(v1.z * inv, v1.w * inv);
    ((uint2*)prow)[tid] = o0;
    ((uint2*)prow)[tid + 256] = o1;
}

// ===========================================================================
extern "C" void kernel_launch(void* const* d_in, const int* in_sizes, int n_in,
                              void* d_out, int out_size)
{
    const float* x  = (const float*)d_in[0];
    const float* Wq = (const float*)d_in[1];
    const float* bq = (const float*)d_in[2];
    const float* Wk = (const float*)d_in[3];
    const float* bk = (const float*)d_in[4];
    const float* Wv = (const float*)d_in[5];
    const float* bv = (const float*)d_in[6];
    float* out = (float*)d_out;

    bf16 *xt, *Wqk, *Wvb, *QK, *Vp, *Pp;
    float *Sp, *bqk;
    cudaGetSymbolAddress((void**)&xt,  g_xt);
    cudaGetSymbolAddress((void**)&Wqk, g_Wqk);
    cudaGetSymbolAddress((void**)&Wvb, g_Wv);
    cudaGetSymbolAddress((void**)&bqk, g_bqk);
    cudaGetSymbolAddress((void**)&QK,  g_QK);
    cudaGetSymbolAddress((void**)&Vp,  g_V);
    cudaGetSymbolAddress((void**)&Sp,  g_S);
    cudaGetSymbolAddress((void**)&Pp,  g_P);

    cudaFuncSetAttribute(mma_gemm<0>, cudaFuncAttributeMaxDynamicSharedMemorySize, SMEMB);
    cudaFuncSetAttribute(mma_gemm<1>, cudaFuncAttributeMaxDynamicSharedMemorySize, SMEMB);
    cudaFuncSetAttribute(mma_gemm<2>, cudaFuncAttributeMaxDynamicSharedMemorySize, SMEMB);
    cudaFuncSetAttribute(mma_gemm<3>, cudaFuncAttributeMaxDynamicSharedMemorySize, SMEMB);

    // conversions + packing
    {
        int n4 = (CH_ * C_) / 4;
        cvt_kernel<<<(n4 + 255) / 256, 256>>>((const float4*)Wq, (__nv_bfloat162*)Wqk, n4);
        cvt_kernel<<<(n4 + 255) / 256, 256>>>((const float4*)Wk,
                                              (__nv_bfloat162*)(Wqk + CH_ * C_), n4);
        n4 = (C_ * C_) / 4;
        cvt_kernel<<<(n4 + 255) / 256, 256>>>((const float4*)Wv, (__nv_bfloat162*)Wvb, n4);
        pack_bias<<<2, 256>>>(bq, bk, bqk);
        transpose_cvt<<<dim3(N_ / 32, C_ / 32, B_), 256>>>(x, xt);
    }

    const size_t sXT = (size_t)N_ * C_;
    const size_t sQK = (size_t)N_ * C_;
    const size_t sX  = (size_t)C_ * N_;
    const size_t sS  = (size_t)N_ * N_;

    // QK[n][o] = sum_c xt[n,c] Wqk[o,c] + bqk[o]   (o in 0..511; Q|K packed)
    mma_gemm<1><<<dim3(C_ / 128, N_ / 128, B_), 128, SMEMB>>>(
        xt, Wqk, bqk, nullptr, QK, C_, C_, C_, C_, 1.0f, sXT, 0, sQK, 0);
    // V[c][m] = sum_k Wv[c,k] xt[m,k] + bv[c]
    mma_gemm<2><<<dim3(N_ / 128, C_ / 128, B_), 128, SMEMB>>>(
        Wvb, xt, bv, nullptr, Vp, C_, C_, C_, N_, 1.0f, 0, sXT, sX, 0);
    // S[n][m] = (1/16) sum_c Q[n,c] K[m,c]   (Q = QK+0, K = QK+256, ld 512)
    mma_gemm<0><<<dim3(N_ / 128, N_ / 128, B_), 128, SMEMB>>>(
        QK, QK + CH_, nullptr, nullptr, Sp, CH_, C_, C_, N_, 0.0625f, sQK, sQK, sS, 0);
    // softmax
    softmax_kernel<<<B_ * N_, 256>>>(Sp, Pp);
    // out[c][n] = x[c][n] + sum_m V[c,m] P[n,m]
    mma_gemm<3><<<dim3(N_ / 128, C_ / 128, B_), 128, SMEMB>>>(
        Vp, Pp, nullptr, x, out, N_, N_, N_, N_, 1.0f, sX, sS, sX, sX);
}

// round 9
// speedup vs baseline: 8.1524x; 1.0683x over previous
#include <cuda_runtime.h>
#include <cuda_bf16.h>
#include <cstdint>
#include <string.h>
#include <math.h>

typedef __nv_bfloat16 bf16;

#define B_ 8
#define C_ 512
#define N_ 2048
#define CH_ 256

// ---- device-global scratch ----
__device__ bf16  g_xt [B_ * N_ * C_];             // [n][c] bf16
__device__ bf16  g_Wqk[2 * CH_ * C_];             // rows 0-255 Wq, 256-511 Wk
__device__ bf16  g_Wv [C_ * C_];
__device__ float g_bqk[2 * CH_];                  // packed bq|bk
__device__ bf16  g_QK [B_ * N_ * C_];             // [n][0..255]=Q, [256..511]=K
__device__ bf16  g_V  [B_ * C_ * N_];             // [c][m]
__device__ bf16  g_S  [(size_t)B_ * N_ * N_];     // [n][m] unscaled logits, bf16
__device__ bf16  g_P  [(size_t)B_ * N_ * N_];     // [n][m] probs, bf16

// ===========================================================================
// PTX helpers
// ===========================================================================
__device__ __forceinline__ uint32_t smem_u32(const void* p) {
    uint32_t a;
    asm("{ .reg .u64 t; cvta.to.shared.u64 t, %1; cvt.u32.u64 %0, t; }"
        : "=r"(a) : "l"(p));
    return a;
}
__device__ __forceinline__ void cp_async16(uint32_t dst, const void* src) {
    asm volatile("cp.async.cg.shared.global [%0], [%1], 16;\n" :: "r"(dst), "l"(src));
}
__device__ __forceinline__ void cp_commit() {
    asm volatile("cp.async.commit_group;\n");
}
template<int NW> __device__ __forceinline__ void cp_wait() {
    asm volatile("cp.async.wait_group %0;\n" :: "n"(NW));
}
__device__ __forceinline__ void ldsm4(uint32_t* r, uint32_t addr) {
    asm volatile("ldmatrix.sync.aligned.m8n8.x4.shared.b16 {%0,%1,%2,%3}, [%4];\n"
                 : "=r"(r[0]), "=r"(r[1]), "=r"(r[2]), "=r"(r[3]) : "r"(addr));
}
__device__ __forceinline__ void mma16816(float* c, const uint32_t* a,
                                         uint32_t b0, uint32_t b1) {
    asm volatile(
        "mma.sync.aligned.m16n8k16.row.col.f32.bf16.bf16.f32 "
        "{%0,%1,%2,%3}, {%4,%5,%6,%7}, {%8,%9}, {%0,%1,%2,%3};\n"
        : "+f"(c[0]), "+f"(c[1]), "+f"(c[2]), "+f"(c[3])
        : "r"(a[0]), "r"(a[1]), "r"(a[2]), "r"(a[3]), "r"(b0), "r"(b1));
}
__device__ __forceinline__ uint32_t pack_bf16x2(float lo, float hi) {
    __nv_bfloat162 h = __float22bfloat162_rn(make_float2(lo, hi));
    uint32_t u;
    memcpy(&u, &h, 4);
    return u;
}
__device__ __forceinline__ float2 unpack_bf16x2(uint32_t u) {
    __nv_bfloat162 h;
    memcpy(&h, &u, 4);
    return __bfloat1622float2(h);
}

// ===========================================================================
// K-major SS GEMM: D[i,j] = sum_k A[i,k]*B[j,k] + epilogue
// CTA 128x128, 4 warps (2x2), warp tile 64x64, K-chunks of 64, 3-stage
// cp.async pipeline, XOR-swizzled smem (128-byte rows).
//   MODE 1: bf16 out + bias[j]
//   MODE 2: bf16 out + bias[i]
//   MODE 3: fp32 out + res[i][j]
//   MODE 4: bf16 out (plain)
// ===========================================================================
#define NSTG 3
#define SMEMB (NSTG * 32768)

template<int MODE>
__global__ void __launch_bounds__(128, 2)
mma_gemm(const bf16* __restrict__ Ag, const bf16* __restrict__ Bg,
         const float* __restrict__ bias, const float* __restrict__ res,
         void* __restrict__ Dg, int Ktot, int lda, int ldb, int ldd,
         size_t sA, size_t sB, size_t sD, size_t sRes)
{
    extern __shared__ char smem[];
    const uint32_t s0 = smem_u32(smem);

    const int tid = threadIdx.x, warp = tid >> 5, lane = tid & 31;
    const int bz = blockIdx.z;
    const int i0 = blockIdx.y * 128, j0 = blockIdx.x * 128;
    const bf16* Ab = Ag + sA * bz;
    const bf16* Bb = Bg + sB * bz;

    const int wm = (warp >> 1) * 64;
    const int wn = (warp & 1) * 64;

    const int rAl = lane & 15;
    const int aHalf = lane >> 4;
    const int rBl = (lane & 7) + ((lane & 16) >> 1);
    const int bHalf = (lane >> 3) & 1;

    float acc[4][8][4];
    #pragma unroll
    for (int mi = 0; mi < 4; mi++)
        #pragma unroll
        for (int ni = 0; ni < 8; ni++)
            #pragma unroll
            for (int e = 0; e < 4; e++) acc[mi][ni][e] = 0.0f;

    auto load_stage = [&](int t) {
        const uint32_t base = s0 + (uint32_t)(t % NSTG) * 32768u;
        const int k0 = t * 64;
        #pragma unroll
        for (int it = 0; it < 16; it++) {
            int q = it * 128 + tid;
            int qq = q & 1023;
            int row = qq >> 3, c = qq & 7;
            uint32_t dst = base + (q < 1024 ? 0u : 16384u)
                         + (uint32_t)(row * 128 + ((c ^ (row & 7)) << 4));
            const bf16* src = (q < 1024)
                ? Ab + (size_t)(i0 + row) * lda + k0 + c * 8
                : Bb + (size_t)(j0 + row) * ldb + k0 + c * 8;
            cp_async16(dst, src);
        }
        cp_commit();
    };

    const int T = Ktot >> 6;
    load_stage(0);
    if (T > 1) load_stage(1); else cp_commit();

    for (int t = 0; t < T; t++) {
        if (t + 2 < T) load_stage(t + 2); else cp_commit();
        cp_wait<2>();
        __syncthreads();

        const uint32_t sa = s0 + (uint32_t)(t % NSTG) * 32768u;
        const uint32_t sb = sa + 16384u;
        #pragma unroll
        for (int k16 = 0; k16 < 4; k16++) {
            uint32_t a[4][4], b[4][4];
            #pragma unroll
            for (int mi = 0; mi < 4; mi++) {
                int row = wm + mi * 16 + rAl;
                int ch = 2 * k16 + aHalf;
                ldsm4(a[mi], sa + (uint32_t)(row * 128 + ((ch ^ (row & 7)) << 4)));
            }
            #pragma unroll
            for (int nh = 0; nh < 4; nh++) {
                int row = wn + nh * 16 + rBl;
                int ch = 2 * k16 + bHalf;
                ldsm4(b[nh], sb + (uint32_t)(row * 128 + ((ch ^ (row & 7)) << 4)));
            }
            #pragma unroll
            for (int mi = 0; mi < 4; mi++)
                #pragma unroll
                for (int ni = 0; ni < 8; ni++)
                    mma16816(acc[mi][ni], a[mi],
                             b[ni >> 1][(ni & 1) * 2], b[ni >> 1][(ni & 1) * 2 + 1]);
        }
        __syncthreads();
    }

    // ---- Epilogue ----
    const int er = lane >> 2;
    const int ec = 2 * (lane & 3);
    #pragma unroll
    for (int mi = 0; mi < 4; mi++)
        #pragma unroll
        for (int ni = 0; ni < 8; ni++) {
            const float* a4 = acc[mi][ni];
            int gm = i0 + wm + mi * 16 + er;
            int gn = j0 + wn + ni * 8 + ec;
            if (MODE == 3) {
                float* D = (float*)Dg + sD * bz;
                const float* R = res + sRes * bz;
                float2 r0 = *(const float2*)&R[(size_t)gm * ldd + gn];
                float2 r1 = *(const float2*)&R[(size_t)(gm + 8) * ldd + gn];
                *(float2*)&D[(size_t)gm * ldd + gn] =
                    make_float2(r0.x + a4[0], r0.y + a4[1]);
                *(float2*)&D[(size_t)(gm + 8) * ldd + gn] =
                    make_float2(r1.x + a4[2], r1.y + a4[3]);
            } else if (MODE == 4) {
                bf16* D = (bf16*)Dg + sD * bz;
                *(__nv_bfloat162*)&D[(size_t)gm * ldd + gn] =
                    __float22bfloat162_rn(make_float2(a4[0], a4[1]));
                *(__nv_bfloat162*)&D[(size_t)(gm + 8) * ldd + gn] =
                    __float22bfloat162_rn(make_float2(a4[2], a4[3]));
            } else {
                bf16* D = (bf16*)Dg + sD * bz;
                float b0, b1, b2, b3;
                if (MODE == 1) {
                    b0 = bias[gn]; b1 = bias[gn + 1]; b2 = b0; b3 = b1;
                } else {
                    b0 = b1 = bias[gm]; b2 = b3 = bias[gm + 8];
                }
                *(__nv_bfloat162*)&D[(size_t)gm * ldd + gn] =
                    __float22bfloat162_rn(make_float2(a4[0] + b0, a4[1] + b1));
                *(__nv_bfloat162*)&D[(size_t)(gm + 8) * ldd + gn] =
                    __float22bfloat162_rn(make_float2(a4[2] + b2, a4[3] + b3));
            }
        }
}

// ===========================================================================
// Fused prep: weight conversions + bias pack + x transpose, one launch.
//   blocks [0,128)    : Wq -> g_Wqk rows 0..255
//   blocks [128,256)  : Wk -> g_Wqk rows 256..511
//   blocks [256,512)  : Wv -> g_Wv
//   block  512        : bias pack
//   blocks [513, 513+8192) : x (B,C,N) fp32 -> xt (B,N,C) bf16
// ===========================================================================
__global__ void __launch_bounds__(256)
prep_all(const float* __restrict__ Wq, const float* __restrict__ Wk,
         const float* __restrict__ Wv, const float* __restrict__ bq,
         const float* __restrict__ bk, const float* __restrict__ x)
{
    __shared__ float tile[32][33];
    const int b = blockIdx.x;
    const int tid = threadIdx.x;

    if (b < 512) {
        const float4* src;
        __nv_bfloat162* dst;
        int idx;
        if (b < 128) {
            src = (const float4*)Wq; dst = (__nv_bfloat162*)g_Wqk;
            idx = b * 256 + tid;
        } else if (b < 256) {
            src = (const float4*)Wk; dst = (__nv_bfloat162*)(g_Wqk + CH_ * C_);
            idx = (b - 128) * 256 + tid;
        } else {
            src = (const float4*)Wv; dst = (__nv_bfloat162*)g_Wv;
            idx = (b - 256) * 256 + tid;
        }
        float4 v = src[idx];
        dst[2 * idx]     = __float22bfloat162_rn(make_float2(v.x, v.y));
        dst[2 * idx + 1] = __float22bfloat162_rn(make_float2(v.z, v.w));
        if (b >= 256) {   // Wv is 65536 float4 over 256 blocks -> 256 f4/block
            int idx2 = idx + 256 * 128;   // second half
            float4 v2 = ((const float4*)Wv)[idx2];
            dst[2 * idx2]     = __float22bfloat162_rn(make_float2(v2.x, v2.y));
            dst[2 * idx2 + 1] = __float22bfloat162_rn(make_float2(v2.z, v2.w));
        }
    } else if (b == 512) {
        g_bqk[tid]        = bq[tid];
        g_bqk[tid + CH_]  = bk[tid];
    } else {
        int t = b - 513;
        int bx = t & 63;            // n tile (N_/32 = 64)
        int by = (t >> 6) & 15;     // c tile (C_/32 = 16)
        int bz = t >> 10;           // batch
        const int c0 = by * 32, n0 = bx * 32;
        const float* xb = x + (size_t)bz * C_ * N_;
        bf16* xtb = g_xt + (size_t)bz * N_ * C_;
        const int tx = tid & 31, ty = tid >> 5;
        #pragma unroll
        for (int i = 0; i < 4; i++)
            tile[ty + 8 * i][tx] = xb[(size_t)(c0 + ty + 8 * i) * N_ + n0 + tx];
        __syncthreads();
        #pragma unroll
        for (int i = 0; i < 4; i++)
            xtb[(size_t)(n0 + ty + 8 * i) * C_ + c0 + tx] =
                __float2bfloat16(tile[tx][ty + 8 * i]);
    }
}

// ===========================================================================
// Softmax over last dim (2048). bf16 in (unscaled logits, scale 1/16 applied
// at load), bf16 out. One 256-thread block per row, one uint4 per thread.
// ===========================================================================
__global__ void __launch_bounds__(256)
softmax_kernel(const bf16* __restrict__ S, bf16* __restrict__ P)
{
    const uint4* row = (const uint4*)(S + (size_t)blockIdx.x * N_);
    uint4* prow = (uint4*)(P + (size_t)blockIdx.x * N_);
    const int tid = threadIdx.x;

    uint4 u = row[tid];
    float v[8];
    {
        float2 f;
        f = unpack_bf16x2(u.x); v[0] = f.x * 0.0625f; v[1] = f.y * 0.0625f;
        f = unpack_bf16x2(u.y); v[2] = f.x * 0.0625f; v[3] = f.y * 0.0625f;
        f = unpack_bf16x2(u.z); v[4] = f.x * 0.0625f; v[5] = f.y * 0.0625f;
        f = unpack_bf16x2(u.w); v[6] = f.x * 0.0625f; v[7] = f.y * 0.0625f;
    }
    float mx = v[0];
    #pragma unroll
    for (int i = 1; i < 8; i++) mx = fmaxf(mx, v[i]);
    #pragma unroll
    for (int o = 16; o; o >>= 1) mx = fmaxf(mx, __shfl_xor_sync(0xFFFFFFFFu, mx, o));
    __shared__ float smax[8], ssum[8];
    if ((tid & 31) == 0) smax[tid >> 5] = mx;
    __syncthreads();
    mx = smax[0];
    #pragma unroll
    for (int w = 1; w < 8; w++) mx = fmaxf(mx, smax[w]);

    float sum = 0.0f;
    #pragma unroll
    for (int i = 0; i < 8; i++) { v[i] = __expf(v[i] - mx); sum += v[i]; }
    #pragma unroll
    for (int o = 16; o; o >>= 1) sum += __shfl_xor_sync(0xFFFFFFFFu, sum, o);
    if ((tid & 31) == 0) ssum[tid >> 5] = sum;
    __syncthreads();
    sum = ssum[0];
    #pragma unroll
    for (int w = 1; w < 8; w++) sum += ssum[w];

    float inv = 1.0f / sum;
    uint4 o4;
    o4.x = pack_bf16x2(v[0] * inv, v[1] * inv);
    o4.y = pack_bf16x2(v[2] * inv, v[3] * inv);
    o4.z = pack_bf16x2(v[4] * inv, v[5] * inv);
    o4.w = pack_bf16x2(v[6] * inv, v[7] * inv);
    prow[tid] = o4;
}

// ===========================================================================
extern "C" void kernel_launch(void* const* d_in, const int* in_sizes, int n_in,
                              void* d_out, int out_size)
{
    const float* x  = (const float*)d_in[0];
    const float* Wq = (const float*)d_in[1];
    const float* bq = (const float*)d_in[2];
    const float* Wk = (const float*)d_in[3];
    const float* bk = (const float*)d_in[4];
    const float* Wv = (const float*)d_in[5];
    const float* bv = (const float*)d_in[6];
    float* out = (float*)d_out;

    bf16 *xt, *Wqk, *Wvb, *QK, *Vp, *Sp, *Pp;
    float *bqk;
    cudaGetSymbolAddress((void**)&xt,  g_xt);
    cudaGetSymbolAddress((void**)&Wqk, g_Wqk);
    cudaGetSymbolAddress((void**)&Wvb, g_Wv);
    cudaGetSymbolAddress((void**)&bqk, g_bqk);
    cudaGetSymbolAddress((void**)&QK,  g_QK);
    cudaGetSymbolAddress((void**)&Vp,  g_V);
    cudaGetSymbolAddress((void**)&Sp,  g_S);
    cudaGetSymbolAddress((void**)&Pp,  g_P);

    cudaFuncSetAttribute(mma_gemm<1>, cudaFuncAttributeMaxDynamicSharedMemorySize, SMEMB);
    cudaFuncSetAttribute(mma_gemm<2>, cudaFuncAttributeMaxDynamicSharedMemorySize, SMEMB);
    cudaFuncSetAttribute(mma_gemm<3>, cudaFuncAttributeMaxDynamicSharedMemorySize, SMEMB);
    cudaFuncSetAttribute(mma_gemm<4>, cudaFuncAttributeMaxDynamicSharedMemorySize, SMEMB);

    // fused prep
    prep_all<<<513 + 8192, 256>>>(Wq, Wk, Wv, bq, bk, x);

    const size_t sXT = (size_t)N_ * C_;
    const size_t sQK = (size_t)N_ * C_;
    const size_t sX  = (size_t)C_ * N_;
    const size_t sS  = (size_t)N_ * N_;

    // QK[n][o] = sum_c xt[n,c] Wqk[o,c] + bqk[o]
    mma_gemm<1><<<dim3(C_ / 128, N_ / 128, B_), 128, SMEMB>>>(
        xt, Wqk, bqk, nullptr, QK, C_, C_, C_, C_, sXT, 0, sQK, 0);
    // V[c][m] = sum_k Wv[c,k] xt[m,k] + bv[c]
    mma_gemm<2><<<dim3(N_ / 128, C_ / 128, B_), 128, SMEMB>>>(
        Wvb, xt, bv, nullptr, Vp, C_, C_, C_, N_, 0, sXT, sX, 0);
    // S[n][m] = sum_c Q[n,c] K[m,c]   (unscaled, bf16 out)
    mma_gemm<4><<<dim3(N_ / 128, N_ / 128, B_), 128, SMEMB>>>(
        QK, QK + CH_, nullptr, nullptr, Sp, CH_, C_, C_, N_, sQK, sQK, sS, 0);
    // softmax (applies 1/16 scaling at load)
    softmax_kernel<<<B_ * N_, 256>>>(Sp, Pp);
    // out[c][n] = x[c][n] + sum_m V[c,m] P[n,m]
    mma_gemm<3><<<dim3(N_ / 128, C_ / 128, B_), 128, SMEMB>>>(
        Vp, Pp, nullptr, x, out, N_, N_, N_, N_, sX, sS, sX, sX);
}